// round 2
// baseline (speedup 1.0000x reference)
#include <cuda_runtime.h>
#include <math.h>
#include <stddef.h>

// ---------------------------------------------------------------------------
// NeuralODE: 10 RK4 steps, dynamics = 3-layer MLP (tanh, tanh, linear).
// All elementwise work (t-concat bias, tanh, RK4 combines) fused into GEMM
// epilogues. 120 GEMM launches of [8192x1024]x[1024x1024] fp32.
// ---------------------------------------------------------------------------

#define MDIM 8192
#define NDIM 1024
#define KDIM 1024
#define STEPS_N 10

enum EpiMode { EPI_TANH = 0, EPI_K1 = 1, EPI_KMID = 2, EPI_K4 = 3 };

constexpr int BM = 128, BN = 128, BK = 16;
constexpr int NT = 256;
constexpr int BMP = BM + 4;  // pad to reduce transposed-store bank conflicts

// Scratch: h, x(dyn input), y1, y2, ksum  -> 5 x 32MB
__device__ float g_scratch[5ull * MDIM * NDIM];

__device__ __forceinline__ float4 ld4(const float* p) { return *(const float4*)p; }
__device__ __forceinline__ void st4(float* p, float4 v) { *(float4*)p = v; }

__device__ __forceinline__ void ld8(float* d, const float* p) {
    float4 x = ld4(p), y = ld4(p + 4);
    d[0] = x.x; d[1] = x.y; d[2] = x.z; d[3] = x.w;
    d[4] = y.x; d[5] = y.y; d[6] = y.z; d[7] = y.w;
}
__device__ __forceinline__ void st8(float* p, const float* d) {
    st4(p,     make_float4(d[0], d[1], d[2], d[3]));
    st4(p + 4, make_float4(d[4], d[5], d[6], d[7]));
}

__device__ __forceinline__ float fast_tanh(float x) {
    float r;
    asm("tanh.approx.f32 %0, %1;" : "=f"(r) : "f"(x));
    return r;
}

__device__ __forceinline__ void mma_tile(const float (*Asb)[BMP],
                                         const float (*Bsb)[BN],
                                         int cm, int cn, float acc[8][8]) {
#pragma unroll
    for (int k = 0; k < BK; k++) {
        float4 av0 = *(const float4*)&Asb[k][cm];
        float4 av1 = *(const float4*)&Asb[k][cm + 4];
        float4 bv0 = *(const float4*)&Bsb[k][cn];
        float4 bv1 = *(const float4*)&Bsb[k][cn + 4];
        float av[8] = {av0.x, av0.y, av0.z, av0.w, av1.x, av1.y, av1.z, av1.w};
        float bv[8] = {bv0.x, bv0.y, bv0.z, bv0.w, bv1.x, bv1.y, bv1.z, bv1.w};
#pragma unroll
        for (int i = 0; i < 8; i++)
#pragma unroll
            for (int j = 0; j < 8; j++)
                acc[i][j] = fmaf(av[i], bv[j], acc[i][j]);
    }
}

template <int EPI>
__global__ void __launch_bounds__(NT)
fused_gemm_kernel(const float* __restrict__ A,     // [M,K] activations
                  const float* __restrict__ W,     // [K,N]
                  const float* __restrict__ bias,  // [N]
                  const float* __restrict__ trow,  // [N] or null (W1 last row)
                  float tval,
                  float* __restrict__ Cout,        // EPI_TANH output
                  const float* __restrict__ hbase, // h at step start
                  float* __restrict__ ksum,
                  float* __restrict__ htmp,        // next dynamics input
                  float* __restrict__ hout,        // EPI_K4 output
                  float coef) {
    __shared__ float As[2][BK][BMP];
    __shared__ float Bs[2][BK][BN];

    const int tid = threadIdx.x;
    const int bm = blockIdx.y * BM;
    const int bn = blockIdx.x * BN;

    const int a_row  = tid >> 2;         // 0..63
    const int a_col4 = (tid & 3) << 2;   // 0,4,8,12
    const int b_row  = tid >> 5;         // 0..7
    const int b_col4 = (tid & 31) << 2;  // 0..124

    const int tx = tid & 15;
    const int ty = tid >> 4;
    const int cm = ty << 3;
    const int cn = tx << 3;

    const float* Abase = A + (size_t)bm * KDIM;
    const float* Wbase = W + bn;

    float acc[8][8];
#pragma unroll
    for (int i = 0; i < 8; i++)
#pragma unroll
        for (int j = 0; j < 8; j++) acc[i][j] = 0.f;

    // prologue: tile 0
    float4 a0 = ld4(Abase + (size_t)a_row * KDIM + a_col4);
    float4 a1 = ld4(Abase + (size_t)(a_row + 64) * KDIM + a_col4);
    float4 b0 = ld4(Wbase + (size_t)b_row * NDIM + b_col4);
    float4 b1 = ld4(Wbase + (size_t)(b_row + 8) * NDIM + b_col4);

    As[0][a_col4 + 0][a_row] = a0.x; As[0][a_col4 + 1][a_row] = a0.y;
    As[0][a_col4 + 2][a_row] = a0.z; As[0][a_col4 + 3][a_row] = a0.w;
    As[0][a_col4 + 0][a_row + 64] = a1.x; As[0][a_col4 + 1][a_row + 64] = a1.y;
    As[0][a_col4 + 2][a_row + 64] = a1.z; As[0][a_col4 + 3][a_row + 64] = a1.w;
    st4(&Bs[0][b_row][b_col4], b0);
    st4(&Bs[0][b_row + 8][b_col4], b1);
    __syncthreads();

    const int NKT = KDIM / BK;  // 64
#pragma unroll 1
    for (int kt = 1; kt < NKT; ++kt) {
        const float* Ap = Abase + kt * BK;
        const float* Wp = Wbase + (size_t)kt * BK * NDIM;
        a0 = ld4(Ap + (size_t)a_row * KDIM + a_col4);
        a1 = ld4(Ap + (size_t)(a_row + 64) * KDIM + a_col4);
        b0 = ld4(Wp + (size_t)b_row * NDIM + b_col4);
        b1 = ld4(Wp + (size_t)(b_row + 8) * NDIM + b_col4);

        const int cb = (kt - 1) & 1;
        mma_tile(As[cb], Bs[cb], cm, cn, acc);

        const int nb = kt & 1;
        As[nb][a_col4 + 0][a_row] = a0.x; As[nb][a_col4 + 1][a_row] = a0.y;
        As[nb][a_col4 + 2][a_row] = a0.z; As[nb][a_col4 + 3][a_row] = a0.w;
        As[nb][a_col4 + 0][a_row + 64] = a1.x; As[nb][a_col4 + 1][a_row + 64] = a1.y;
        As[nb][a_col4 + 2][a_row + 64] = a1.z; As[nb][a_col4 + 3][a_row + 64] = a1.w;
        st4(&Bs[nb][b_row][b_col4], b0);
        st4(&Bs[nb][b_row + 8][b_col4], b1);
        __syncthreads();
    }
    mma_tile(As[(NKT - 1) & 1], Bs[(NKT - 1) & 1], cm, cn, acc);

    // -------------------- fused epilogue --------------------
    const int gcol = bn + cn;
    float bb[8];
    ld8(bb, bias + gcol);
    if (EPI == EPI_TANH && trow != nullptr) {
        float tv[8];
        ld8(tv, trow + gcol);
#pragma unroll
        for (int j = 0; j < 8; j++) bb[j] = fmaf(tval, tv[j], bb[j]);
    }

#pragma unroll
    for (int i = 0; i < 8; i++) {
        const size_t idx = (size_t)(bm + cm + i) * NDIM + gcol;
        float v[8];
#pragma unroll
        for (int j = 0; j < 8; j++) v[j] = acc[i][j] + bb[j];

        if (EPI == EPI_TANH) {
            float o[8];
#pragma unroll
            for (int j = 0; j < 8; j++) o[j] = fast_tanh(v[j]);
            st8(Cout + idx, o);
        } else if (EPI == EPI_K1) {
            st8(ksum + idx, v);
            float hv[8];
            ld8(hv, hbase + idx);
            float o[8];
#pragma unroll
            for (int j = 0; j < 8; j++) o[j] = fmaf(coef, v[j], hv[j]);
            st8(htmp + idx, o);
        } else if (EPI == EPI_KMID) {
            float s[8];
            ld8(s, ksum + idx);
#pragma unroll
            for (int j = 0; j < 8; j++) s[j] = fmaf(2.0f, v[j], s[j]);
            st8(ksum + idx, s);
            float hv[8];
            ld8(hv, hbase + idx);
            float o[8];
#pragma unroll
            for (int j = 0; j < 8; j++) o[j] = fmaf(coef, v[j], hv[j]);
            st8(htmp + idx, o);
        } else {  // EPI_K4
            float s[8], hv[8], o[8];
            ld8(s, ksum + idx);
            ld8(hv, hbase + idx);
#pragma unroll
            for (int j = 0; j < 8; j++) o[j] = fmaf(coef, s[j] + v[j], hv[j]);
            st8(hout + idx, o);
        }
    }
}

// ---------------------------------------------------------------------------

template <int EPI>
static inline void launch_gemm(const float* A, const float* W, const float* bias,
                               const float* trow, float tval, float* Cout,
                               const float* hbase, float* ksum, float* htmp,
                               float* hout, float coef) {
    dim3 grid(NDIM / BN, MDIM / BM);
    fused_gemm_kernel<EPI><<<grid, NT>>>(A, W, bias, trow, tval, Cout, hbase,
                                         ksum, htmp, hout, coef);
}

extern "C" void kernel_launch(void* const* d_in, const int* in_sizes, int n_in,
                              void* d_out, int out_size) {
    const float* h0 = (const float*)d_in[0];
    const float* W1 = (const float*)d_in[1];
    const float* b1 = (const float*)d_in[2];
    const float* W2 = (const float*)d_in[3];
    const float* b2 = (const float*)d_in[4];
    const float* W3 = (const float*)d_in[5];
    const float* b3 = (const float*)d_in[6];
    float* out = (float*)d_out;

    float* base = nullptr;
    cudaGetSymbolAddress((void**)&base, g_scratch);
    const size_t SZ = (size_t)MDIM * NDIM;
    float* gh = base;           // h carried between steps
    float* gx = base + SZ;      // dynamics input (h + c*k)
    float* y1 = base + 2 * SZ;  // layer1 activations
    float* y2 = base + 3 * SZ;  // layer2 activations
    float* ks = base + 4 * SZ;  // k1 + 2k2 + 2k3 accumulator

    const float dt = 0.1f;
    const float* trow = W1 + (size_t)KDIM * NDIM;  // W1 row 1024 (the t row)

    for (int s = 0; s < STEPS_N; s++) {
        const float t0 = dt * (float)s;
        const float* hin = (s == 0) ? h0 : gh;
        float* hdst = (s == STEPS_N - 1) ? out : gh;

        // k1 = f(t0, h)
        launch_gemm<EPI_TANH>(hin, W1, b1, trow, t0, y1, nullptr, nullptr, nullptr, nullptr, 0.f);
        launch_gemm<EPI_TANH>(y1, W2, b2, nullptr, 0.f, y2, nullptr, nullptr, nullptr, nullptr, 0.f);
        launch_gemm<EPI_K1>(y2, W3, b3, nullptr, 0.f, nullptr, hin, ks, gx, nullptr, dt * 0.5f);

        // k2 = f(t0+dt/2, h + dt/2*k1)
        launch_gemm<EPI_TANH>(gx, W1, b1, trow, t0 + dt * 0.5f, y1, nullptr, nullptr, nullptr, nullptr, 0.f);
        launch_gemm<EPI_TANH>(y1, W2, b2, nullptr, 0.f, y2, nullptr, nullptr, nullptr, nullptr, 0.f);
        launch_gemm<EPI_KMID>(y2, W3, b3, nullptr, 0.f, nullptr, hin, ks, gx, nullptr, dt * 0.5f);

        // k3 = f(t0+dt/2, h + dt/2*k2)
        launch_gemm<EPI_TANH>(gx, W1, b1, trow, t0 + dt * 0.5f, y1, nullptr, nullptr, nullptr, nullptr, 0.f);
        launch_gemm<EPI_TANH>(y1, W2, b2, nullptr, 0.f, y2, nullptr, nullptr, nullptr, nullptr, 0.f);
        launch_gemm<EPI_KMID>(y2, W3, b3, nullptr, 0.f, nullptr, hin, ks, gx, nullptr, dt);

        // k4 = f(t0+dt, h + dt*k3); h' = h + dt/6*(ksum + k4)
        launch_gemm<EPI_TANH>(gx, W1, b1, trow, t0 + dt, y1, nullptr, nullptr, nullptr, nullptr, 0.f);
        launch_gemm<EPI_TANH>(y1, W2, b2, nullptr, 0.f, y2, nullptr, nullptr, nullptr, nullptr, 0.f);
        launch_gemm<EPI_K4>(y2, W3, b3, nullptr, 0.f, nullptr, hin, ks, nullptr, hdst, dt / 6.0f);
    }
}

// round 4
// speedup vs baseline: 2.4246x; 2.4246x over previous
#include <cuda_runtime.h>
#include <cuda_bf16.h>
#include <math.h>
#include <stddef.h>
#include <stdint.h>

// ---------------------------------------------------------------------------
// NeuralODE via mma.sync bf16 3-term split GEMM (Ah*Bh + Al*Bh + Ah*Bl).
// sm_100 baseline PTX only (no tcgen05 -- harness targets plain sm_100).
// 120 GEMMs of [8192x1024]x[1024x1024]; operands pre-split to bf16 hi/lo in
// global memory; epilogues fuse tanh / RK4 combines AND produce the next
// GEMM's bf16 operands directly.
// ---------------------------------------------------------------------------

#define MDIM 8192
#define NDIM 1024
#define KDIM 1024
#define STEPS_N 10

enum EpiMode { EPI_TANH = 0, EPI_K1 = 1, EPI_KMID = 2, EPI_K4 = 3 };

constexpr int BM = 128, BN = 128, BK = 32;
constexpr int NT = 256;
constexpr int NSTAGES = KDIM / BK;  // 32

// smem tile geometry: 128 rows x 32 bf16, row stride 40 ushorts (80 B).
// 80 = 16*5, 5 coprime with 8 -> ldmatrix rows hit distinct 16B banks.
constexpr int RSB = 80;                   // row stride bytes
constexpr int TILE_B = 128 * RSB;         // 10240
constexpr int T_AH = 0, T_AL = TILE_B, T_BH = 2 * TILE_B, T_BL = 3 * TILE_B;
constexpr int STAGE_B = 4 * TILE_B;       // 40960
constexpr int SMEM_TOTAL = 2 * STAGE_B;   // 81920

// ---- global scratch ------------------------------------------------------
__device__ float g_f32[2ull * MDIM * NDIM];           // gh, ksum
__device__ unsigned short g_bf[8ull * MDIM * NDIM];   // hs(h,l) gx(h,l) y1(h,l) y2(h,l)
__device__ unsigned short g_wt[6ull * KDIM * NDIM];   // w1..w3 (h,l)

// ---- PTX helpers ---------------------------------------------------------

__device__ __forceinline__ uint32_t smem_to_u32(const void* p) {
    uint32_t a;
    asm("{ .reg .u64 t; cvta.to.shared.u64 t, %1; cvt.u32.u64 %0, t; }"
        : "=r"(a) : "l"(p));
    return a;
}

#define CP_ASYNC16(saddr, gptr)                                   \
    asm volatile("cp.async.cg.shared.global [%0], [%1], 16;" ::   \
                     "r"(saddr), "l"(gptr))
#define CP_COMMIT() asm volatile("cp.async.commit_group;" ::: "memory")
#define CP_WAIT1() asm volatile("cp.async.wait_group 1;" ::: "memory")
#define CP_WAIT0() asm volatile("cp.async.wait_group 0;" ::: "memory")

#define LDSM_X4(r0, r1, r2, r3, addr)                                     \
    asm volatile("ldmatrix.sync.aligned.m8n8.x4.shared.b16 "              \
                 "{%0,%1,%2,%3}, [%4];"                                   \
                 : "=r"(r0), "=r"(r1), "=r"(r2), "=r"(r3) : "r"(addr))

#define MMA_BF16(D, A, B)                                                  \
    asm volatile("mma.sync.aligned.m16n8k16.row.col.f32.bf16.bf16.f32 "    \
                 "{%0,%1,%2,%3}, {%4,%5,%6,%7}, {%8,%9}, {%0,%1,%2,%3};"   \
                 : "+f"((D)[0]), "+f"((D)[1]), "+f"((D)[2]), "+f"((D)[3])  \
                 : "r"((A)[0]), "r"((A)[1]), "r"((A)[2]), "r"((A)[3]),     \
                   "r"((B)[0]), "r"((B)[1]))

__device__ __forceinline__ float fast_tanh(float x) {
    float r;
    asm("tanh.approx.f32 %0, %1;" : "=f"(r) : "f"(x));
    return r;
}

__device__ __forceinline__ float4 ld4(const float* p) { return *(const float4*)p; }

__device__ __forceinline__ void cvt_split2(float a, float b,
                                           uint32_t& hp, uint32_t& lp) {
    __nv_bfloat16 ha = __float2bfloat16_rn(a);
    __nv_bfloat16 hb = __float2bfloat16_rn(b);
    __nv_bfloat16 la = __float2bfloat16_rn(a - __bfloat162float(ha));
    __nv_bfloat16 lb = __float2bfloat16_rn(b - __bfloat162float(hb));
    hp = (uint32_t)__bfloat16_as_ushort(ha) |
         ((uint32_t)__bfloat16_as_ushort(hb) << 16);
    lp = (uint32_t)__bfloat16_as_ushort(la) |
         ((uint32_t)__bfloat16_as_ushort(lb) << 16);
}

__device__ __forceinline__ void split_store(unsigned short* oh,
                                            unsigned short* ol, size_t idx,
                                            float a, float b) {
    uint32_t hp, lp;
    cvt_split2(a, b, hp, lp);
    *(uint32_t*)(oh + idx) = hp;
    *(uint32_t*)(ol + idx) = lp;
}

// ---- weight split+transpose: out[n][k] = split(W[k][n]) ------------------

__global__ void wsplit_kernel(const float* __restrict__ W,
                              unsigned short* __restrict__ hi,
                              unsigned short* __restrict__ lo) {
    __shared__ float t[32][33];
    const int tx = threadIdx.x, ty = threadIdx.y;
    const int n0 = blockIdx.x * 32, k0 = blockIdx.y * 32;
#pragma unroll
    for (int j = 0; j < 32; j += 8)
        t[ty + j][tx] = W[(size_t)(k0 + ty + j) * NDIM + n0 + tx];
    __syncthreads();
#pragma unroll
    for (int j = 0; j < 32; j += 8) {
        float v = t[tx][ty + j];
        __nv_bfloat16 h = __float2bfloat16_rn(v);
        __nv_bfloat16 l = __float2bfloat16_rn(v - __bfloat162float(h));
        size_t o = (size_t)(n0 + ty + j) * KDIM + k0 + tx;
        hi[o] = __bfloat16_as_ushort(h);
        lo[o] = __bfloat16_as_ushort(l);
    }
}

// ---- activation split (h0 prologue) --------------------------------------

__global__ void asplit_kernel(const float* __restrict__ X,
                              unsigned short* __restrict__ hi,
                              unsigned short* __restrict__ lo) {
    size_t i = ((size_t)blockIdx.x * blockDim.x + threadIdx.x) * 4;
    float4 v = ld4(X + i);
    uint32_t h0, l0, h1, l1;
    cvt_split2(v.x, v.y, h0, l0);
    cvt_split2(v.z, v.w, h1, l1);
    *(uint2*)(hi + i) = make_uint2(h0, h1);
    *(uint2*)(lo + i) = make_uint2(l0, l1);
}

// ---- fused epilogue per (row, col-pair) ----------------------------------

template <int EPI>
__device__ __forceinline__ void epi_rc(int m, int c, float v0, float v1,
                                       unsigned short* oh, unsigned short* ol,
                                       const float* hbase, float* ksum,
                                       float* hout, float coef) {
    const size_t idx = (size_t)m * NDIM + c;
    if (EPI == EPI_TANH) {
        split_store(oh, ol, idx, fast_tanh(v0), fast_tanh(v1));
    } else if (EPI == EPI_K1) {
        *(float2*)(ksum + idx) = make_float2(v0, v1);
        float2 h = *(const float2*)(hbase + idx);
        split_store(oh, ol, idx, fmaf(coef, v0, h.x), fmaf(coef, v1, h.y));
    } else if (EPI == EPI_KMID) {
        float2 s = *(float2*)(ksum + idx);
        s.x = fmaf(2.f, v0, s.x);
        s.y = fmaf(2.f, v1, s.y);
        *(float2*)(ksum + idx) = s;
        float2 h = *(const float2*)(hbase + idx);
        split_store(oh, ol, idx, fmaf(coef, v0, h.x), fmaf(coef, v1, h.y));
    } else {  // EPI_K4
        float2 s = *(const float2*)(ksum + idx);
        float2 h = *(const float2*)(hbase + idx);
        float g0 = fmaf(coef, s.x + v0, h.x);
        float g1 = fmaf(coef, s.y + v1, h.y);
        *(float2*)(hout + idx) = make_float2(g0, g1);
        split_store(oh, ol, idx, g0, g1);
    }
}

// ---- main GEMM -----------------------------------------------------------

template <int EPI>
__global__ void __launch_bounds__(NT)
ngemm_kernel(const unsigned short* __restrict__ Ah,
             const unsigned short* __restrict__ Al,
             const unsigned short* __restrict__ Bh,
             const unsigned short* __restrict__ Bl,
             const float* __restrict__ bias,
             const float* __restrict__ trow, float tval,
             unsigned short* __restrict__ oh, unsigned short* __restrict__ ol,
             const float* __restrict__ hbase, float* __restrict__ ksum,
             float* __restrict__ hout, float coef) {
    extern __shared__ char smc[];
    const uint32_t sb = smem_to_u32(smc);
    const int tid = threadIdx.x;
    const int lane = tid & 31;
    const int w = tid >> 5;
    const int wm = w & 1;        // 2 m-tiles of 64
    const int wn = w >> 1;       // 4 n-tiles of 32
    const int bm = blockIdx.y * BM;
    const int bn = blockIdx.x * BN;

    // cp.async chunk mapping: 512 chunks (16B) per tile, 2 per thread
    const int ch0 = tid, ch1 = tid + NT;
    const int r0 = ch0 >> 2, e0 = (ch0 & 3) * 8;
    const int r1 = ch1 >> 2, e1 = (ch1 & 3) * 8;
    const unsigned short* gah0 = Ah + (size_t)(bm + r0) * KDIM + e0;
    const unsigned short* gah1 = Ah + (size_t)(bm + r1) * KDIM + e1;
    const unsigned short* gal0 = Al + (size_t)(bm + r0) * KDIM + e0;
    const unsigned short* gal1 = Al + (size_t)(bm + r1) * KDIM + e1;
    const unsigned short* gbh0 = Bh + (size_t)(bn + r0) * KDIM + e0;
    const unsigned short* gbh1 = Bh + (size_t)(bn + r1) * KDIM + e1;
    const unsigned short* gbl0 = Bl + (size_t)(bn + r0) * KDIM + e0;
    const unsigned short* gbl1 = Bl + (size_t)(bn + r1) * KDIM + e1;
    const uint32_t s0 = (uint32_t)(r0 * RSB + (ch0 & 3) * 16);
    const uint32_t s1 = (uint32_t)(r1 * RSB + (ch1 & 3) * 16);

    // ldmatrix per-lane offsets
    const uint32_t a_off = (uint32_t)((lane & 15) * RSB + ((lane & 16) ? 16 : 0));
    const uint32_t b_off = (uint32_t)(((lane & 7) + ((lane & 16) ? 8 : 0)) * RSB +
                                      ((lane & 8) ? 16 : 0));

    float acc[4][4][4];
#pragma unroll
    for (int i = 0; i < 4; i++)
#pragma unroll
        for (int j = 0; j < 4; j++)
#pragma unroll
            for (int q = 0; q < 4; q++) acc[i][j][q] = 0.f;

    // prologue: stage 0
    {
        const uint32_t base = sb;
        CP_ASYNC16(base + T_AH + s0, gah0);
        CP_ASYNC16(base + T_AH + s1, gah1);
        CP_ASYNC16(base + T_AL + s0, gal0);
        CP_ASYNC16(base + T_AL + s1, gal1);
        CP_ASYNC16(base + T_BH + s0, gbh0);
        CP_ASYNC16(base + T_BH + s1, gbh1);
        CP_ASYNC16(base + T_BL + s0, gbl0);
        CP_ASYNC16(base + T_BL + s1, gbl1);
        CP_COMMIT();
    }

#pragma unroll 1
    for (int s = 0; s < NSTAGES; ++s) {
        if (s + 1 < NSTAGES) {
            const int kc = (s + 1) * BK;
            const uint32_t base = sb + ((s + 1) & 1) * STAGE_B;
            CP_ASYNC16(base + T_AH + s0, gah0 + kc);
            CP_ASYNC16(base + T_AH + s1, gah1 + kc);
            CP_ASYNC16(base + T_AL + s0, gal0 + kc);
            CP_ASYNC16(base + T_AL + s1, gal1 + kc);
            CP_ASYNC16(base + T_BH + s0, gbh0 + kc);
            CP_ASYNC16(base + T_BH + s1, gbh1 + kc);
            CP_ASYNC16(base + T_BL + s0, gbl0 + kc);
            CP_ASYNC16(base + T_BL + s1, gbl1 + kc);
            CP_COMMIT();
            CP_WAIT1();
        } else {
            CP_WAIT0();
        }
        __syncthreads();

        const uint32_t base = sb + (s & 1) * STAGE_B;
#pragma unroll
        for (int ks = 0; ks < 2; ++ks) {
            uint32_t ah_[4][4], al_[4][4], bh_[4][2], bl_[4][2];
#pragma unroll
            for (int i = 0; i < 4; ++i) {
                const uint32_t ra =
                    base + (uint32_t)((wm * 64 + i * 16) * RSB + ks * 32) + a_off;
                LDSM_X4(ah_[i][0], ah_[i][1], ah_[i][2], ah_[i][3], ra + T_AH);
                LDSM_X4(al_[i][0], al_[i][1], al_[i][2], al_[i][3], ra + T_AL);
            }
#pragma unroll
            for (int jj = 0; jj < 2; ++jj) {
                const uint32_t rb =
                    base + (uint32_t)((wn * 32 + jj * 16) * RSB + ks * 32) + b_off;
                uint32_t t0, t1, t2, t3;
                LDSM_X4(t0, t1, t2, t3, rb + T_BH);
                bh_[2 * jj][0] = t0; bh_[2 * jj][1] = t1;
                bh_[2 * jj + 1][0] = t2; bh_[2 * jj + 1][1] = t3;
                LDSM_X4(t0, t1, t2, t3, rb + T_BL);
                bl_[2 * jj][0] = t0; bl_[2 * jj][1] = t1;
                bl_[2 * jj + 1][0] = t2; bl_[2 * jj + 1][1] = t3;
            }
#pragma unroll
            for (int i = 0; i < 4; ++i)
#pragma unroll
                for (int j = 0; j < 4; ++j) {
                    MMA_BF16(acc[i][j], ah_[i], bh_[j]);
                    MMA_BF16(acc[i][j], al_[i], bh_[j]);
                    MMA_BF16(acc[i][j], ah_[i], bl_[j]);
                }
        }
        __syncthreads();
    }

    // ---------------- epilogue -------------------------------------------
#pragma unroll
    for (int j = 0; j < 4; ++j) {
        const int c = bn + wn * 32 + j * 8 + (lane & 3) * 2;
        float bb0 = bias[c], bb1 = bias[c + 1];
        if (EPI == EPI_TANH && trow != nullptr) {
            bb0 = fmaf(tval, trow[c], bb0);
            bb1 = fmaf(tval, trow[c + 1], bb1);
        }
#pragma unroll
        for (int i = 0; i < 4; ++i) {
            const int m0 = bm + wm * 64 + i * 16 + (lane >> 2);
            epi_rc<EPI>(m0, c, acc[i][j][0] + bb0, acc[i][j][1] + bb1,
                        oh, ol, hbase, ksum, hout, coef);
            epi_rc<EPI>(m0 + 8, c, acc[i][j][2] + bb0, acc[i][j][3] + bb1,
                        oh, ol, hbase, ksum, hout, coef);
        }
    }
}

// ---------------------------------------------------------------------------

template <int EPI>
static inline void launch_gemm(const unsigned short* Ah, const unsigned short* Al,
                               const unsigned short* Bh, const unsigned short* Bl,
                               const float* bias, const float* trow, float tval,
                               unsigned short* oh, unsigned short* ol,
                               const float* hbase, float* ksum, float* hout,
                               float coef) {
    dim3 grid(NDIM / BN, MDIM / BM);
    ngemm_kernel<EPI><<<grid, NT, SMEM_TOTAL>>>(Ah, Al, Bh, Bl, bias, trow,
                                                tval, oh, ol, hbase, ksum,
                                                hout, coef);
}

extern "C" void kernel_launch(void* const* d_in, const int* in_sizes, int n_in,
                              void* d_out, int out_size) {
    const float* h0 = (const float*)d_in[0];
    const float* W1 = (const float*)d_in[1];
    const float* b1 = (const float*)d_in[2];
    const float* W2 = (const float*)d_in[3];
    const float* b2 = (const float*)d_in[4];
    const float* W3 = (const float*)d_in[5];
    const float* b3 = (const float*)d_in[6];
    float* out = (float*)d_out;

    cudaFuncSetAttribute(ngemm_kernel<EPI_TANH>,
                         cudaFuncAttributeMaxDynamicSharedMemorySize, SMEM_TOTAL);
    cudaFuncSetAttribute(ngemm_kernel<EPI_K1>,
                         cudaFuncAttributeMaxDynamicSharedMemorySize, SMEM_TOTAL);
    cudaFuncSetAttribute(ngemm_kernel<EPI_KMID>,
                         cudaFuncAttributeMaxDynamicSharedMemorySize, SMEM_TOTAL);
    cudaFuncSetAttribute(ngemm_kernel<EPI_K4>,
                         cudaFuncAttributeMaxDynamicSharedMemorySize, SMEM_TOTAL);

    float* fbase = nullptr;
    cudaGetSymbolAddress((void**)&fbase, g_f32);
    unsigned short* abase = nullptr;
    cudaGetSymbolAddress((void**)&abase, g_bf);
    unsigned short* wbase = nullptr;
    cudaGetSymbolAddress((void**)&wbase, g_wt);

    const size_t SZ = (size_t)MDIM * NDIM;
    float* gh = fbase;
    float* ks = fbase + SZ;

    unsigned short* hsh = abase;
    unsigned short* hsl = abase + SZ;
    unsigned short* gxh = abase + 2 * SZ;
    unsigned short* gxl = abase + 3 * SZ;
    unsigned short* y1h = abase + 4 * SZ;
    unsigned short* y1l = abase + 5 * SZ;
    unsigned short* y2h = abase + 6 * SZ;
    unsigned short* y2l = abase + 7 * SZ;

    const size_t WSZ = (size_t)KDIM * NDIM;
    unsigned short* w1h = wbase;
    unsigned short* w1l = wbase + WSZ;
    unsigned short* w2h = wbase + 2 * WSZ;
    unsigned short* w2l = wbase + 3 * WSZ;
    unsigned short* w3h = wbase + 4 * WSZ;
    unsigned short* w3l = wbase + 5 * WSZ;

    // one-time operand prep
    {
        dim3 g(NDIM / 32, KDIM / 32), b(32, 8);
        wsplit_kernel<<<g, b>>>(W1, w1h, w1l);
        wsplit_kernel<<<g, b>>>(W2, w2h, w2l);
        wsplit_kernel<<<g, b>>>(W3, w3h, w3l);
        asplit_kernel<<<(int)(SZ / 4 / 256), 256>>>(h0, hsh, hsl);
    }

    const float dt = 0.1f;
    const float* trow = W1 + (size_t)KDIM * NDIM;  // W1 row 1024 (t row)

    for (int s = 0; s < STEPS_N; s++) {
        const float t0 = dt * (float)s;
        const float* hin = (s == 0) ? h0 : gh;
        float* hdst = (s == STEPS_N - 1) ? out : gh;

        // k1 = f(t0, h)
        launch_gemm<EPI_TANH>(hsh, hsl, w1h, w1l, b1, trow, t0, y1h, y1l, nullptr, nullptr, nullptr, 0.f);
        launch_gemm<EPI_TANH>(y1h, y1l, w2h, w2l, b2, nullptr, 0.f, y2h, y2l, nullptr, nullptr, nullptr, 0.f);
        launch_gemm<EPI_K1>(y2h, y2l, w3h, w3l, b3, nullptr, 0.f, gxh, gxl, hin, ks, nullptr, dt * 0.5f);
        // k2 = f(t0+dt/2, h + dt/2*k1)
        launch_gemm<EPI_TANH>(gxh, gxl, w1h, w1l, b1, trow, t0 + dt * 0.5f, y1h, y1l, nullptr, nullptr, nullptr, 0.f);
        launch_gemm<EPI_TANH>(y1h, y1l, w2h, w2l, b2, nullptr, 0.f, y2h, y2l, nullptr, nullptr, nullptr, 0.f);
        launch_gemm<EPI_KMID>(y2h, y2l, w3h, w3l, b3, nullptr, 0.f, gxh, gxl, hin, ks, nullptr, dt * 0.5f);
        // k3 = f(t0+dt/2, h + dt/2*k2)
        launch_gemm<EPI_TANH>(gxh, gxl, w1h, w1l, b1, trow, t0 + dt * 0.5f, y1h, y1l, nullptr, nullptr, nullptr, 0.f);
        launch_gemm<EPI_TANH>(y1h, y1l, w2h, w2l, b2, nullptr, 0.f, y2h, y2l, nullptr, nullptr, nullptr, 0.f);
        launch_gemm<EPI_KMID>(y2h, y2l, w3h, w3l, b3, nullptr, 0.f, gxh, gxl, hin, ks, nullptr, dt);
        // k4 = f(t0+dt, h + dt*k3); h' = h + dt/6*(ksum + k4)
        launch_gemm<EPI_TANH>(gxh, gxl, w1h, w1l, b1, trow, t0 + dt, y1h, y1l, nullptr, nullptr, nullptr, 0.f);
        launch_gemm<EPI_TANH>(y1h, y1l, w2h, w2l, b2, nullptr, 0.f, y2h, y2l, nullptr, nullptr, nullptr, 0.f);
        launch_gemm<EPI_K4>(y2h, y2l, w3h, w3l, b3, nullptr, 0.f, hsh, hsl, hin, ks, hdst, dt / 6.0f);
    }
}

// round 5
// speedup vs baseline: 3.3814x; 1.3947x over previous
#include <cuda_runtime.h>
#include <cuda_fp16.h>
#include <math.h>
#include <stddef.h>
#include <stdint.h>

// ---------------------------------------------------------------------------
// NeuralODE via mma.sync fp16 2-term split GEMM:  A*W ~= Ah*Wh + Ah*Wl
// (A single fp16 -- its rounding error ~2^-11 decorrelates across evals;
//  W split hi/lo fp16 -- captured exactly to ~2^-22).
// 120 GEMMs of [8192x1024]x[1024x1024]; epilogues fuse tanh / RK4 combines
// and emit the next GEMM's fp16 activations directly.
// ---------------------------------------------------------------------------

#define MDIM 8192
#define NDIM 1024
#define KDIM 1024
#define STEPS_N 10

enum EpiMode { EPI_TANH = 0, EPI_K1 = 1, EPI_KMID = 2, EPI_K4 = 3 };

constexpr int BM = 128, BN = 128, BK = 32;
constexpr int NT = 256;
constexpr int NSTAGES = KDIM / BK;  // 32
constexpr int NBUF = 3;

// smem tile: 128 rows x 32 fp16, row stride 80 B (16*5, conflict-free ldsm)
constexpr int RSB = 80;
constexpr int TILE_B = 128 * RSB;          // 10240
constexpr int T_A = 0, T_BH = TILE_B, T_BL = 2 * TILE_B;
constexpr int STAGE_B = 3 * TILE_B;        // 30720
constexpr int SMEM_TOTAL = NBUF * STAGE_B; // 92160

// ---- global scratch ------------------------------------------------------
__device__ float g_f32[2ull * MDIM * NDIM];           // gh, ksum
__device__ unsigned short g_bf[4ull * MDIM * NDIM];   // hs, gx, y1, y2 (fp16)
__device__ unsigned short g_wt[6ull * KDIM * NDIM];   // w1..w3 (hi,lo fp16)

// ---- PTX helpers ---------------------------------------------------------

__device__ __forceinline__ uint32_t smem_to_u32(const void* p) {
    uint32_t a;
    asm("{ .reg .u64 t; cvta.to.shared.u64 t, %1; cvt.u32.u64 %0, t; }"
        : "=r"(a) : "l"(p));
    return a;
}

#define CP_ASYNC16(saddr, gptr)                                   \
    asm volatile("cp.async.cg.shared.global [%0], [%1], 16;" ::   \
                     "r"(saddr), "l"(gptr))
#define CP_COMMIT() asm volatile("cp.async.commit_group;" ::: "memory")
#define CP_WAIT2() asm volatile("cp.async.wait_group 2;" ::: "memory")
#define CP_WAIT1() asm volatile("cp.async.wait_group 1;" ::: "memory")
#define CP_WAIT0() asm volatile("cp.async.wait_group 0;" ::: "memory")

#define LDSM_X4(r0, r1, r2, r3, addr)                                     \
    asm volatile("ldmatrix.sync.aligned.m8n8.x4.shared.b16 "              \
                 "{%0,%1,%2,%3}, [%4];"                                   \
                 : "=r"(r0), "=r"(r1), "=r"(r2), "=r"(r3) : "r"(addr))

#define MMA_F16(D, A, B)                                                   \
    asm volatile("mma.sync.aligned.m16n8k16.row.col.f32.f16.f16.f32 "      \
                 "{%0,%1,%2,%3}, {%4,%5,%6,%7}, {%8,%9}, {%0,%1,%2,%3};"   \
                 : "+f"((D)[0]), "+f"((D)[1]), "+f"((D)[2]), "+f"((D)[3])  \
                 : "r"((A)[0]), "r"((A)[1]), "r"((A)[2]), "r"((A)[3]),     \
                   "r"((B)[0]), "r"((B)[1]))

__device__ __forceinline__ float fast_tanh(float x) {
    float r;
    asm("tanh.approx.f32 %0, %1;" : "=f"(r) : "f"(x));
    return r;
}

__device__ __forceinline__ float4 ld4(const float* p) { return *(const float4*)p; }

__device__ __forceinline__ uint32_t pack_h2(float a, float b) {
    __half2 h = __floats2half2_rn(a, b);
    return *(uint32_t*)&h;
}

// ---- weight split+transpose: out[n][k] = fp16 split of W[k][n] -----------

__global__ void wsplit_kernel(const float* __restrict__ W,
                              unsigned short* __restrict__ hi,
                              unsigned short* __restrict__ lo) {
    __shared__ float t[32][33];
    const int tx = threadIdx.x, ty = threadIdx.y;
    const int n0 = blockIdx.x * 32, k0 = blockIdx.y * 32;
#pragma unroll
    for (int j = 0; j < 32; j += 8)
        t[ty + j][tx] = W[(size_t)(k0 + ty + j) * NDIM + n0 + tx];
    __syncthreads();
#pragma unroll
    for (int j = 0; j < 32; j += 8) {
        float v = t[tx][ty + j];
        __half h = __float2half_rn(v);
        __half l = __float2half_rn(v - __half2float(h));
        size_t o = (size_t)(n0 + ty + j) * KDIM + k0 + tx;
        hi[o] = *(unsigned short*)&h;
        lo[o] = *(unsigned short*)&l;
    }
}

// ---- activation convert (h0 prologue) ------------------------------------

__global__ void asplit_kernel(const float* __restrict__ X,
                              unsigned short* __restrict__ hi) {
    size_t i = ((size_t)blockIdx.x * blockDim.x + threadIdx.x) * 4;
    float4 v = ld4(X + i);
    *(uint2*)(hi + i) = make_uint2(pack_h2(v.x, v.y), pack_h2(v.z, v.w));
}

// ---- fused epilogue per (row, col-pair) ----------------------------------

template <int EPI>
__device__ __forceinline__ void epi_rc(int m, int c, float v0, float v1,
                                       unsigned short* oh,
                                       const float* hbase, float* ksum,
                                       float* hout, float coef) {
    const size_t idx = (size_t)m * NDIM + c;
    if (EPI == EPI_TANH) {
        *(uint32_t*)(oh + idx) = pack_h2(fast_tanh(v0), fast_tanh(v1));
    } else if (EPI == EPI_K1) {
        *(float2*)(ksum + idx) = make_float2(v0, v1);
        float2 h = *(const float2*)(hbase + idx);
        *(uint32_t*)(oh + idx) =
            pack_h2(fmaf(coef, v0, h.x), fmaf(coef, v1, h.y));
    } else if (EPI == EPI_KMID) {
        float2 s = *(float2*)(ksum + idx);
        s.x = fmaf(2.f, v0, s.x);
        s.y = fmaf(2.f, v1, s.y);
        *(float2*)(ksum + idx) = s;
        float2 h = *(const float2*)(hbase + idx);
        *(uint32_t*)(oh + idx) =
            pack_h2(fmaf(coef, v0, h.x), fmaf(coef, v1, h.y));
    } else {  // EPI_K4
        float2 s = *(const float2*)(ksum + idx);
        float2 h = *(const float2*)(hbase + idx);
        float g0 = fmaf(coef, s.x + v0, h.x);
        float g1 = fmaf(coef, s.y + v1, h.y);
        *(float2*)(hout + idx) = make_float2(g0, g1);
        *(uint32_t*)(oh + idx) = pack_h2(g0, g1);
    }
}

// ---- main GEMM -----------------------------------------------------------

template <int EPI>
__global__ void __launch_bounds__(NT)
ngemm_kernel(const unsigned short* __restrict__ Ax,
             const unsigned short* __restrict__ Bh,
             const unsigned short* __restrict__ Bl,
             const float* __restrict__ bias,
             const float* __restrict__ trow, float tval,
             unsigned short* __restrict__ oh,
             const float* __restrict__ hbase, float* __restrict__ ksum,
             float* __restrict__ hout, float coef) {
    extern __shared__ char smc[];
    const uint32_t sb = smem_to_u32(smc);
    const int tid = threadIdx.x;
    const int lane = tid & 31;
    const int w = tid >> 5;
    const int wm = w & 1;
    const int wn = w >> 1;
    const int bm = blockIdx.y * BM;
    const int bn = blockIdx.x * BN;

    // cp.async chunk mapping: 512 x 16B chunks per tile, 2 per thread
    const int ch0 = tid, ch1 = tid + NT;
    const int r0 = ch0 >> 2, e0 = (ch0 & 3) * 8;
    const int r1 = ch1 >> 2, e1 = (ch1 & 3) * 8;
    const unsigned short* ga0 = Ax + (size_t)(bm + r0) * KDIM + e0;
    const unsigned short* ga1 = Ax + (size_t)(bm + r1) * KDIM + e1;
    const unsigned short* gbh0 = Bh + (size_t)(bn + r0) * KDIM + e0;
    const unsigned short* gbh1 = Bh + (size_t)(bn + r1) * KDIM + e1;
    const unsigned short* gbl0 = Bl + (size_t)(bn + r0) * KDIM + e0;
    const unsigned short* gbl1 = Bl + (size_t)(bn + r1) * KDIM + e1;
    const uint32_t s0 = (uint32_t)(r0 * RSB + (ch0 & 3) * 16);
    const uint32_t s1 = (uint32_t)(r1 * RSB + (ch1 & 3) * 16);

    const uint32_t a_off = (uint32_t)((lane & 15) * RSB + ((lane & 16) ? 16 : 0));
    const uint32_t b_off = (uint32_t)(((lane & 7) + ((lane & 16) ? 8 : 0)) * RSB +
                                      ((lane & 8) ? 16 : 0));

    float acc[4][4][4];
#pragma unroll
    for (int i = 0; i < 4; i++)
#pragma unroll
        for (int j = 0; j < 4; j++)
#pragma unroll
            for (int q = 0; q < 4; q++) acc[i][j][q] = 0.f;

#define ISSUE_STAGE(st)                                                   \
    do {                                                                  \
        const int _kc = (st) * BK;                                        \
        const uint32_t _b = sb + ((st) % NBUF) * STAGE_B;                 \
        CP_ASYNC16(_b + T_A + s0, ga0 + _kc);                             \
        CP_ASYNC16(_b + T_A + s1, ga1 + _kc);                             \
        CP_ASYNC16(_b + T_BH + s0, gbh0 + _kc);                           \
        CP_ASYNC16(_b + T_BH + s1, gbh1 + _kc);                           \
        CP_ASYNC16(_b + T_BL + s0, gbl0 + _kc);                           \
        CP_ASYNC16(_b + T_BL + s1, gbl1 + _kc);                           \
        CP_COMMIT();                                                      \
    } while (0)

    ISSUE_STAGE(0);
    ISSUE_STAGE(1);

#pragma unroll 1
    for (int s = 0; s < NSTAGES; ++s) {
        __syncthreads();  // all warps done with buffer (s-1)%NBUF
        if (s + 2 < NSTAGES) {
            ISSUE_STAGE(s + 2);
            CP_WAIT2();
        } else if (s + 1 < NSTAGES) {
            CP_WAIT1();
        } else {
            CP_WAIT0();
        }
        __syncthreads();

        const uint32_t base = sb + (s % NBUF) * STAGE_B;
#pragma unroll
        for (int ks = 0; ks < 2; ++ks) {
            uint32_t a_[4][4], bh_[4][2], bl_[4][2];
#pragma unroll
            for (int i = 0; i < 4; ++i) {
                const uint32_t ra =
                    base + (uint32_t)((wm * 64 + i * 16) * RSB + ks * 32) + a_off;
                LDSM_X4(a_[i][0], a_[i][1], a_[i][2], a_[i][3], ra + T_A);
            }
#pragma unroll
            for (int jj = 0; jj < 2; ++jj) {
                const uint32_t rb =
                    base + (uint32_t)((wn * 32 + jj * 16) * RSB + ks * 32) + b_off;
                uint32_t t0, t1, t2, t3;
                LDSM_X4(t0, t1, t2, t3, rb + T_BH);
                bh_[2 * jj][0] = t0; bh_[2 * jj][1] = t1;
                bh_[2 * jj + 1][0] = t2; bh_[2 * jj + 1][1] = t3;
                LDSM_X4(t0, t1, t2, t3, rb + T_BL);
                bl_[2 * jj][0] = t0; bl_[2 * jj][1] = t1;
                bl_[2 * jj + 1][0] = t2; bl_[2 * jj + 1][1] = t3;
            }
#pragma unroll
            for (int i = 0; i < 4; ++i)
#pragma unroll
                for (int j = 0; j < 4; ++j) {
                    MMA_F16(acc[i][j], a_[i], bh_[j]);
                    MMA_F16(acc[i][j], a_[i], bl_[j]);
                }
        }
    }
#undef ISSUE_STAGE

    // ---------------- epilogue -------------------------------------------
#pragma unroll
    for (int j = 0; j < 4; ++j) {
        const int c = bn + wn * 32 + j * 8 + (lane & 3) * 2;
        float bb0 = bias[c], bb1 = bias[c + 1];
        if (EPI == EPI_TANH && trow != nullptr) {
            bb0 = fmaf(tval, trow[c], bb0);
            bb1 = fmaf(tval, trow[c + 1], bb1);
        }
#pragma unroll
        for (int i = 0; i < 4; ++i) {
            const int m0 = bm + wm * 64 + i * 16 + (lane >> 2);
            epi_rc<EPI>(m0, c, acc[i][j][0] + bb0, acc[i][j][1] + bb1,
                        oh, hbase, ksum, hout, coef);
            epi_rc<EPI>(m0 + 8, c, acc[i][j][2] + bb0, acc[i][j][3] + bb1,
                        oh, hbase, ksum, hout, coef);
        }
    }
}

// ---------------------------------------------------------------------------

template <int EPI>
static inline void launch_gemm(const unsigned short* Ax,
                               const unsigned short* Bh, const unsigned short* Bl,
                               const float* bias, const float* trow, float tval,
                               unsigned short* oh, const float* hbase,
                               float* ksum, float* hout, float coef) {
    dim3 grid(NDIM / BN, MDIM / BM);
    ngemm_kernel<EPI><<<grid, NT, SMEM_TOTAL>>>(Ax, Bh, Bl, bias, trow, tval,
                                                oh, hbase, ksum, hout, coef);
}

extern "C" void kernel_launch(void* const* d_in, const int* in_sizes, int n_in,
                              void* d_out, int out_size) {
    const float* h0 = (const float*)d_in[0];
    const float* W1 = (const float*)d_in[1];
    const float* b1 = (const float*)d_in[2];
    const float* W2 = (const float*)d_in[3];
    const float* b2 = (const float*)d_in[4];
    const float* W3 = (const float*)d_in[5];
    const float* b3 = (const float*)d_in[6];
    float* out = (float*)d_out;

    cudaFuncSetAttribute(ngemm_kernel<EPI_TANH>,
                         cudaFuncAttributeMaxDynamicSharedMemorySize, SMEM_TOTAL);
    cudaFuncSetAttribute(ngemm_kernel<EPI_K1>,
                         cudaFuncAttributeMaxDynamicSharedMemorySize, SMEM_TOTAL);
    cudaFuncSetAttribute(ngemm_kernel<EPI_KMID>,
                         cudaFuncAttributeMaxDynamicSharedMemorySize, SMEM_TOTAL);
    cudaFuncSetAttribute(ngemm_kernel<EPI_K4>,
                         cudaFuncAttributeMaxDynamicSharedMemorySize, SMEM_TOTAL);

    float* fbase = nullptr;
    cudaGetSymbolAddress((void**)&fbase, g_f32);
    unsigned short* abase = nullptr;
    cudaGetSymbolAddress((void**)&abase, g_bf);
    unsigned short* wbase = nullptr;
    cudaGetSymbolAddress((void**)&wbase, g_wt);

    const size_t SZ = (size_t)MDIM * NDIM;
    float* gh = fbase;
    float* ks = fbase + SZ;

    unsigned short* hs = abase;            // h as fp16
    unsigned short* gx = abase + SZ;       // dynamics input fp16
    unsigned short* y1 = abase + 2 * SZ;
    unsigned short* y2 = abase + 3 * SZ;

    const size_t WSZ = (size_t)KDIM * NDIM;
    unsigned short* w1h = wbase;
    unsigned short* w1l = wbase + WSZ;
    unsigned short* w2h = wbase + 2 * WSZ;
    unsigned short* w2l = wbase + 3 * WSZ;
    unsigned short* w3h = wbase + 4 * WSZ;
    unsigned short* w3l = wbase + 5 * WSZ;

    {
        dim3 g(NDIM / 32, KDIM / 32), b(32, 8);
        wsplit_kernel<<<g, b>>>(W1, w1h, w1l);
        wsplit_kernel<<<g, b>>>(W2, w2h, w2l);
        wsplit_kernel<<<g, b>>>(W3, w3h, w3l);
        asplit_kernel<<<(int)(SZ / 4 / 256), 256>>>(h0, hs);
    }

    const float dt = 0.1f;
    const float* trow = W1 + (size_t)KDIM * NDIM;  // W1 row 1024 (t row)

    for (int s = 0; s < STEPS_N; s++) {
        const float t0 = dt * (float)s;
        const float* hin = (s == 0) ? h0 : gh;
        float* hdst = (s == STEPS_N - 1) ? out : gh;

        // k1 = f(t0, h)
        launch_gemm<EPI_TANH>(hs, w1h, w1l, b1, trow, t0, y1, nullptr, nullptr, nullptr, 0.f);
        launch_gemm<EPI_TANH>(y1, w2h, w2l, b2, nullptr, 0.f, y2, nullptr, nullptr, nullptr, 0.f);
        launch_gemm<EPI_K1>(y2, w3h, w3l, b3, nullptr, 0.f, gx, hin, ks, nullptr, dt * 0.5f);
        // k2
        launch_gemm<EPI_TANH>(gx, w1h, w1l, b1, trow, t0 + dt * 0.5f, y1, nullptr, nullptr, nullptr, 0.f);
        launch_gemm<EPI_TANH>(y1, w2h, w2l, b2, nullptr, 0.f, y2, nullptr, nullptr, nullptr, 0.f);
        launch_gemm<EPI_KMID>(y2, w3h, w3l, b3, nullptr, 0.f, gx, hin, ks, nullptr, dt * 0.5f);
        // k3
        launch_gemm<EPI_TANH>(gx, w1h, w1l, b1, trow, t0 + dt * 0.5f, y1, nullptr, nullptr, nullptr, 0.f);
        launch_gemm<EPI_TANH>(y1, w2h, w2l, b2, nullptr, 0.f, y2, nullptr, nullptr, nullptr, 0.f);
        launch_gemm<EPI_KMID>(y2, w3h, w3l, b3, nullptr, 0.f, gx, hin, ks, nullptr, dt);
        // k4 + combine
        launch_gemm<EPI_TANH>(gx, w1h, w1l, b1, trow, t0 + dt, y1, nullptr, nullptr, nullptr, 0.f);
        launch_gemm<EPI_TANH>(y1, w2h, w2l, b2, nullptr, 0.f, y2, nullptr, nullptr, nullptr, 0.f);
        launch_gemm<EPI_K4>(y2, w3h, w3l, b3, nullptr, 0.f, hs, hin, ks, hdst, dt / 6.0f);
    }
}

// round 6
// speedup vs baseline: 5.2424x; 1.5504x over previous
#include <cuda_runtime.h>
#include <cuda_fp16.h>
#include <math.h>
#include <stddef.h>
#include <stdint.h>

// ---------------------------------------------------------------------------
// NeuralODE via single-precision-fp16 mma.sync GEMM:  A*W ~= Ah*Wh
// (both operands rounded to fp16; measured error budget from R4/R5 says the
//  ~2^-11 rounding contributes ~1e-5..1e-4 end-to-end vs 1e-3 threshold).
// 120 GEMMs of [8192x1024]x[1024x1024]; epilogues fuse tanh / RK4 combines
// and emit the next GEMM's fp16 activations directly.
// ---------------------------------------------------------------------------

#define MDIM 8192
#define NDIM 1024
#define KDIM 1024
#define STEPS_N 10

enum EpiMode { EPI_TANH = 0, EPI_K1 = 1, EPI_KMID = 2, EPI_K4 = 3 };

constexpr int BM = 128, BN = 128, BK = 32;
constexpr int NT = 256;
constexpr int NSTAGES = KDIM / BK;  // 32
constexpr int NBUF = 4;

// smem tile: 128 rows x 32 fp16, row stride 80 B (16*5, conflict-free ldsm)
constexpr int RSB = 80;
constexpr int TILE_B = 128 * RSB;          // 10240
constexpr int T_A = 0, T_B = TILE_B;
constexpr int STAGE_B = 2 * TILE_B;        // 20480
constexpr int SMEM_TOTAL = NBUF * STAGE_B; // 81920

// ---- global scratch ------------------------------------------------------
__device__ float g_f32[2ull * MDIM * NDIM];           // gh, ksum
__device__ unsigned short g_bf[4ull * MDIM * NDIM];   // hs, gx, y1, y2 (fp16)
__device__ unsigned short g_wt[3ull * KDIM * NDIM];   // w1..w3 (fp16)

// ---- PTX helpers ---------------------------------------------------------

__device__ __forceinline__ uint32_t smem_to_u32(const void* p) {
    uint32_t a;
    asm("{ .reg .u64 t; cvta.to.shared.u64 t, %1; cvt.u32.u64 %0, t; }"
        : "=r"(a) : "l"(p));
    return a;
}

#define CP_ASYNC16(saddr, gptr)                                   \
    asm volatile("cp.async.cg.shared.global [%0], [%1], 16;" ::   \
                     "r"(saddr), "l"(gptr))
#define CP_COMMIT() asm volatile("cp.async.commit_group;" ::: "memory")
#define CP_WAIT3() asm volatile("cp.async.wait_group 3;" ::: "memory")
#define CP_WAIT2() asm volatile("cp.async.wait_group 2;" ::: "memory")
#define CP_WAIT1() asm volatile("cp.async.wait_group 1;" ::: "memory")
#define CP_WAIT0() asm volatile("cp.async.wait_group 0;" ::: "memory")

#define LDSM_X4(r0, r1, r2, r3, addr)                                     \
    asm volatile("ldmatrix.sync.aligned.m8n8.x4.shared.b16 "              \
                 "{%0,%1,%2,%3}, [%4];"                                   \
                 : "=r"(r0), "=r"(r1), "=r"(r2), "=r"(r3) : "r"(addr))

#define MMA_F16(D, A, B)                                                   \
    asm volatile("mma.sync.aligned.m16n8k16.row.col.f32.f16.f16.f32 "      \
                 "{%0,%1,%2,%3}, {%4,%5,%6,%7}, {%8,%9}, {%0,%1,%2,%3};"   \
                 : "+f"((D)[0]), "+f"((D)[1]), "+f"((D)[2]), "+f"((D)[3])  \
                 : "r"((A)[0]), "r"((A)[1]), "r"((A)[2]), "r"((A)[3]),     \
                   "r"((B)[0]), "r"((B)[1]))

__device__ __forceinline__ float fast_tanh(float x) {
    float r;
    asm("tanh.approx.f32 %0, %1;" : "=f"(r) : "f"(x));
    return r;
}

__device__ __forceinline__ float4 ld4(const float* p) { return *(const float4*)p; }

__device__ __forceinline__ uint32_t pack_h2(float a, float b) {
    __half2 h = __floats2half2_rn(a, b);
    return *(uint32_t*)&h;
}

// ---- weight convert+transpose: out[n][k] = fp16(W[k][n]) -----------------

__global__ void wsplit_kernel(const float* __restrict__ W,
                              unsigned short* __restrict__ hi) {
    __shared__ float t[32][33];
    const int tx = threadIdx.x, ty = threadIdx.y;
    const int n0 = blockIdx.x * 32, k0 = blockIdx.y * 32;
#pragma unroll
    for (int j = 0; j < 32; j += 8)
        t[ty + j][tx] = W[(size_t)(k0 + ty + j) * NDIM + n0 + tx];
    __syncthreads();
#pragma unroll
    for (int j = 0; j < 32; j += 8) {
        float v = t[tx][ty + j];
        __half h = __float2half_rn(v);
        hi[(size_t)(n0 + ty + j) * KDIM + k0 + tx] = *(unsigned short*)&h;
    }
}

// ---- activation convert (h0 prologue) ------------------------------------

__global__ void asplit_kernel(const float* __restrict__ X,
                              unsigned short* __restrict__ hi) {
    size_t i = ((size_t)blockIdx.x * blockDim.x + threadIdx.x) * 4;
    float4 v = ld4(X + i);
    *(uint2*)(hi + i) = make_uint2(pack_h2(v.x, v.y), pack_h2(v.z, v.w));
}

// ---- fused epilogue per (row, col-pair) ----------------------------------

template <int EPI>
__device__ __forceinline__ void epi_rc(int m, int c, float v0, float v1,
                                       unsigned short* oh,
                                       const float* hbase, float* ksum,
                                       float* hout, float coef) {
    const size_t idx = (size_t)m * NDIM + c;
    if (EPI == EPI_TANH) {
        *(uint32_t*)(oh + idx) = pack_h2(fast_tanh(v0), fast_tanh(v1));
    } else if (EPI == EPI_K1) {
        *(float2*)(ksum + idx) = make_float2(v0, v1);
        float2 h = *(const float2*)(hbase + idx);
        *(uint32_t*)(oh + idx) =
            pack_h2(fmaf(coef, v0, h.x), fmaf(coef, v1, h.y));
    } else if (EPI == EPI_KMID) {
        float2 s = *(float2*)(ksum + idx);
        s.x = fmaf(2.f, v0, s.x);
        s.y = fmaf(2.f, v1, s.y);
        *(float2*)(ksum + idx) = s;
        float2 h = *(const float2*)(hbase + idx);
        *(uint32_t*)(oh + idx) =
            pack_h2(fmaf(coef, v0, h.x), fmaf(coef, v1, h.y));
    } else {  // EPI_K4
        float2 s = *(const float2*)(ksum + idx);
        float2 h = *(const float2*)(hbase + idx);
        float g0 = fmaf(coef, s.x + v0, h.x);
        float g1 = fmaf(coef, s.y + v1, h.y);
        *(float2*)(hout + idx) = make_float2(g0, g1);
        *(uint32_t*)(oh + idx) = pack_h2(g0, g1);
    }
}

// ---- main GEMM -----------------------------------------------------------

template <int EPI>
__global__ void __launch_bounds__(NT)
ngemm_kernel(const unsigned short* __restrict__ Ax,
             const unsigned short* __restrict__ Bx,
             const float* __restrict__ bias,
             const float* __restrict__ trow, float tval,
             unsigned short* __restrict__ oh,
             const float* __restrict__ hbase, float* __restrict__ ksum,
             float* __restrict__ hout, float coef) {
    extern __shared__ char smc[];
    const uint32_t sb = smem_to_u32(smc);
    const int tid = threadIdx.x;
    const int lane = tid & 31;
    const int w = tid >> 5;
    const int wm = w & 1;
    const int wn = w >> 1;
    const int bm = blockIdx.y * BM;
    const int bn = blockIdx.x * BN;

    // cp.async chunk mapping: 512 x 16B chunks per tile, 2 per thread
    const int ch0 = tid, ch1 = tid + NT;
    const int r0 = ch0 >> 2, e0 = (ch0 & 3) * 8;
    const int r1 = ch1 >> 2, e1 = (ch1 & 3) * 8;
    const unsigned short* ga0 = Ax + (size_t)(bm + r0) * KDIM + e0;
    const unsigned short* ga1 = Ax + (size_t)(bm + r1) * KDIM + e1;
    const unsigned short* gb0 = Bx + (size_t)(bn + r0) * KDIM + e0;
    const unsigned short* gb1 = Bx + (size_t)(bn + r1) * KDIM + e1;
    const uint32_t s0 = (uint32_t)(r0 * RSB + (ch0 & 3) * 16);
    const uint32_t s1 = (uint32_t)(r1 * RSB + (ch1 & 3) * 16);

    const uint32_t a_off = (uint32_t)((lane & 15) * RSB + ((lane & 16) ? 16 : 0));
    const uint32_t b_off = (uint32_t)(((lane & 7) + ((lane & 16) ? 8 : 0)) * RSB +
                                      ((lane & 8) ? 16 : 0));

    float acc[4][4][4];
#pragma unroll
    for (int i = 0; i < 4; i++)
#pragma unroll
        for (int j = 0; j < 4; j++)
#pragma unroll
            for (int q = 0; q < 4; q++) acc[i][j][q] = 0.f;

#define ISSUE_STAGE(st)                                                   \
    do {                                                                  \
        const int _kc = (st) * BK;                                        \
        const uint32_t _b = sb + ((st) % NBUF) * STAGE_B;                 \
        CP_ASYNC16(_b + T_A + s0, ga0 + _kc);                             \
        CP_ASYNC16(_b + T_A + s1, ga1 + _kc);                             \
        CP_ASYNC16(_b + T_B + s0, gb0 + _kc);                             \
        CP_ASYNC16(_b + T_B + s1, gb1 + _kc);                             \
        CP_COMMIT();                                                      \
    } while (0)

    ISSUE_STAGE(0);
    ISSUE_STAGE(1);
    ISSUE_STAGE(2);

#pragma unroll 1
    for (int s = 0; s < NSTAGES; ++s) {
        __syncthreads();  // all warps done with the buffer being refilled
        if (s + 3 < NSTAGES) {
            ISSUE_STAGE(s + 3);
            CP_WAIT3();
        } else if (s + 2 < NSTAGES) {
            CP_WAIT2();
        } else if (s + 1 < NSTAGES) {
            CP_WAIT1();
        } else {
            CP_WAIT0();
        }
        __syncthreads();

        const uint32_t base = sb + (s % NBUF) * STAGE_B;
#pragma unroll
        for (int ks = 0; ks < 2; ++ks) {
            uint32_t a_[4][4], b_[4][2];
#pragma unroll
            for (int i = 0; i < 4; ++i) {
                const uint32_t ra =
                    base + (uint32_t)((wm * 64 + i * 16) * RSB + ks * 32) + a_off;
                LDSM_X4(a_[i][0], a_[i][1], a_[i][2], a_[i][3], ra + T_A);
            }
#pragma unroll
            for (int jj = 0; jj < 2; ++jj) {
                const uint32_t rb =
                    base + (uint32_t)((wn * 32 + jj * 16) * RSB + ks * 32) + b_off;
                uint32_t t0, t1, t2, t3;
                LDSM_X4(t0, t1, t2, t3, rb + T_B);
                b_[2 * jj][0] = t0; b_[2 * jj][1] = t1;
                b_[2 * jj + 1][0] = t2; b_[2 * jj + 1][1] = t3;
            }
#pragma unroll
            for (int i = 0; i < 4; ++i)
#pragma unroll
                for (int j = 0; j < 4; ++j) {
                    MMA_F16(acc[i][j], a_[i], b_[j]);
                }
        }
    }
#undef ISSUE_STAGE

    // ---------------- epilogue -------------------------------------------
#pragma unroll
    for (int j = 0; j < 4; ++j) {
        const int c = bn + wn * 32 + j * 8 + (lane & 3) * 2;
        float bb0 = bias[c], bb1 = bias[c + 1];
        if (EPI == EPI_TANH && trow != nullptr) {
            bb0 = fmaf(tval, trow[c], bb0);
            bb1 = fmaf(tval, trow[c + 1], bb1);
        }
#pragma unroll
        for (int i = 0; i < 4; ++i) {
            const int m0 = bm + wm * 64 + i * 16 + (lane >> 2);
            epi_rc<EPI>(m0, c, acc[i][j][0] + bb0, acc[i][j][1] + bb1,
                        oh, hbase, ksum, hout, coef);
            epi_rc<EPI>(m0 + 8, c, acc[i][j][2] + bb0, acc[i][j][3] + bb1,
                        oh, hbase, ksum, hout, coef);
        }
    }
}

// ---------------------------------------------------------------------------

template <int EPI>
static inline void launch_gemm(const unsigned short* Ax, const unsigned short* Bx,
                               const float* bias, const float* trow, float tval,
                               unsigned short* oh, const float* hbase,
                               float* ksum, float* hout, float coef) {
    dim3 grid(NDIM / BN, MDIM / BM);
    ngemm_kernel<EPI><<<grid, NT, SMEM_TOTAL>>>(Ax, Bx, bias, trow, tval,
                                                oh, hbase, ksum, hout, coef);
}

extern "C" void kernel_launch(void* const* d_in, const int* in_sizes, int n_in,
                              void* d_out, int out_size) {
    const float* h0 = (const float*)d_in[0];
    const float* W1 = (const float*)d_in[1];
    const float* b1 = (const float*)d_in[2];
    const float* W2 = (const float*)d_in[3];
    const float* b2 = (const float*)d_in[4];
    const float* W3 = (const float*)d_in[5];
    const float* b3 = (const float*)d_in[6];
    float* out = (float*)d_out;

    cudaFuncSetAttribute(ngemm_kernel<EPI_TANH>,
                         cudaFuncAttributeMaxDynamicSharedMemorySize, SMEM_TOTAL);
    cudaFuncSetAttribute(ngemm_kernel<EPI_K1>,
                         cudaFuncAttributeMaxDynamicSharedMemorySize, SMEM_TOTAL);
    cudaFuncSetAttribute(ngemm_kernel<EPI_KMID>,
                         cudaFuncAttributeMaxDynamicSharedMemorySize, SMEM_TOTAL);
    cudaFuncSetAttribute(ngemm_kernel<EPI_K4>,
                         cudaFuncAttributeMaxDynamicSharedMemorySize, SMEM_TOTAL);

    float* fbase = nullptr;
    cudaGetSymbolAddress((void**)&fbase, g_f32);
    unsigned short* abase = nullptr;
    cudaGetSymbolAddress((void**)&abase, g_bf);
    unsigned short* wbase = nullptr;
    cudaGetSymbolAddress((void**)&wbase, g_wt);

    const size_t SZ = (size_t)MDIM * NDIM;
    float* gh = fbase;
    float* ks = fbase + SZ;

    unsigned short* hs = abase;            // h as fp16
    unsigned short* gx = abase + SZ;       // dynamics input fp16
    unsigned short* y1 = abase + 2 * SZ;
    unsigned short* y2 = abase + 3 * SZ;

    const size_t WSZ = (size_t)KDIM * NDIM;
    unsigned short* w1x = wbase;
    unsigned short* w2x = wbase + WSZ;
    unsigned short* w3x = wbase + 2 * WSZ;

    {
        dim3 g(NDIM / 32, KDIM / 32), b(32, 8);
        wsplit_kernel<<<g, b>>>(W1, w1x);
        wsplit_kernel<<<g, b>>>(W2, w2x);
        wsplit_kernel<<<g, b>>>(W3, w3x);
        asplit_kernel<<<(int)(SZ / 4 / 256), 256>>>(h0, hs);
    }

    const float dt = 0.1f;
    const float* trow = W1 + (size_t)KDIM * NDIM;  // W1 row 1024 (t row)

    for (int s = 0; s < STEPS_N; s++) {
        const float t0 = dt * (float)s;
        const float* hin = (s == 0) ? h0 : gh;
        float* hdst = (s == STEPS_N - 1) ? out : gh;

        // k1 = f(t0, h)
        launch_gemm<EPI_TANH>(hs, w1x, b1, trow, t0, y1, nullptr, nullptr, nullptr, 0.f);
        launch_gemm<EPI_TANH>(y1, w2x, b2, nullptr, 0.f, y2, nullptr, nullptr, nullptr, 0.f);
        launch_gemm<EPI_K1>(y2, w3x, b3, nullptr, 0.f, gx, hin, ks, nullptr, dt * 0.5f);
        // k2
        launch_gemm<EPI_TANH>(gx, w1x, b1, trow, t0 + dt * 0.5f, y1, nullptr, nullptr, nullptr, 0.f);
        launch_gemm<EPI_TANH>(y1, w2x, b2, nullptr, 0.f, y2, nullptr, nullptr, nullptr, 0.f);
        launch_gemm<EPI_KMID>(y2, w3x, b3, nullptr, 0.f, gx, hin, ks, nullptr, dt * 0.5f);
        // k3
        launch_gemm<EPI_TANH>(gx, w1x, b1, trow, t0 + dt * 0.5f, y1, nullptr, nullptr, nullptr, 0.f);
        launch_gemm<EPI_TANH>(y1, w2x, b2, nullptr, 0.f, y2, nullptr, nullptr, nullptr, 0.f);
        launch_gemm<EPI_KMID>(y2, w3x, b3, nullptr, 0.f, gx, hin, ks, nullptr, dt);
        // k4 + combine
        launch_gemm<EPI_TANH>(gx, w1x, b1, trow, t0 + dt, y1, nullptr, nullptr, nullptr, 0.f);
        launch_gemm<EPI_TANH>(y1, w2x, b2, nullptr, 0.f, y2, nullptr, nullptr, nullptr, 0.f);
        launch_gemm<EPI_K4>(y2, w3x, b3, nullptr, 0.f, hs, hin, ks, hdst, dt / 6.0f);
    }
}